// round 11
// baseline (speedup 1.0000x reference)
#include <cuda_runtime.h>
#include <mma.h>
#include <cstdint>

using namespace nvcuda;

#define N_NODES 50000
#define MAX_E   800000
#define D 96
#define D4 (D/4)
#define GROWS 96                             // rows per gemm block
#define NBLK ((N_NODES + 255) / 256)         // 196 scan blocks

// ---- device scratch (zero-init at load; k_agg restores counter zeros) ----
__device__ int   g_deg_out_i[N_NODES];
__device__ int   g_deg_in_i[N_NODES];
__device__ int   g_row_ptr[N_NODES + 1];
__device__ int   g_fill[N_NODES];
__device__ int   g_bsum[256];
__device__ int   g_csr_src[MAX_E];
__device__ float g_h[(size_t)N_NODES * D];   // (x@W) * inv_sqrt(deg_out)

// ---- degree kernels (split so each stream waits only on what it needs) ----
__global__ void k_deg_out(const int* __restrict__ src, int E) {
    int e = blockIdx.x * blockDim.x + threadIdx.x;
    if (e < E) atomicAdd(&g_deg_out_i[src[e]], 1);
}
__global__ void k_deg_in(const int* __restrict__ dst, int E) {
    int e = blockIdx.x * blockDim.x + threadIdx.x;
    if (e < E) atomicAdd(&g_deg_in_i[dst[e]], 1);
}

// ---- scan step 1: per-block exclusive scan of deg_in ----
__global__ void k_scan1() {
    __shared__ int sh[256];
    int i = blockIdx.x * 256 + threadIdx.x;
    int v = (i < N_NODES) ? g_deg_in_i[i] : 0;
    sh[threadIdx.x] = v;
    __syncthreads();
    #pragma unroll
    for (int off = 1; off < 256; off <<= 1) {
        int t = (threadIdx.x >= off) ? sh[threadIdx.x - off] : 0;
        __syncthreads();
        sh[threadIdx.x] += t;
        __syncthreads();
    }
    if (i < N_NODES) g_row_ptr[i] = sh[threadIdx.x] - v;
    if (threadIdx.x == 255) g_bsum[blockIdx.x] = sh[255];
}

// ---- scan steps 2+3 fused: every block scans the 196 block sums itself ----
__global__ void k_scan23(int E) {
    __shared__ int sh[256];
    int t = threadIdx.x;
    int v = (t < NBLK) ? g_bsum[t] : 0;
    sh[t] = v;
    __syncthreads();
    #pragma unroll
    for (int off = 1; off < 256; off <<= 1) {
        int u = (t >= off) ? sh[t - off] : 0;
        __syncthreads();
        sh[t] += u;
        __syncthreads();
    }
    int base = (blockIdx.x > 0) ? sh[blockIdx.x - 1] : 0;

    int i = blockIdx.x * 256 + t;
    if (i < N_NODES) {
        int p = g_row_ptr[i] + base;
        g_row_ptr[i] = p;
        g_fill[i] = p;
    }
    if (i == 0) g_row_ptr[N_NODES] = E;
}

// ---- kernel: bucket edges by dst ----
__global__ void k_fill(const int* __restrict__ src,
                       const int* __restrict__ dst, int E) {
    int e = blockIdx.x * blockDim.x + threadIdx.x;
    if (e < E) {
        int d = dst[e];
        int pos = atomicAdd(&g_fill[d], 1);
        g_csr_src[pos] = src[e];
    }
}

// ---- kernel: h = (x@W) * inv_sqrt(deg_out), tf32 tensor cores, 3-term comp ----
// 96 rows/block, 6 warps; warp w owns rows [16w,16w+16), all 96 cols.
__global__ __launch_bounds__(192)
void k_gemm(const float* __restrict__ x, const float* __restrict__ Wg) {
    __shared__ float xs[GROWS * D];          // 36864 B (staging + epilogue reuse)
    const int tid = threadIdx.x;
    const int rbase = blockIdx.x * GROWS;

    // stage x tile (zero-padded -> handles last partial block safely)
    for (int i = tid; i < GROWS * D4; i += 192) {
        int r = i / D4, c = i % D4;
        int g = rbase + r;
        float4 v = make_float4(0.f, 0.f, 0.f, 0.f);
        if (g < N_NODES) v = ((const float4*)(x + (size_t)g * D))[c];
        ((float4*)xs)[i] = v;
    }
    __syncthreads();

    const int warp = tid >> 5;

    wmma::fragment<wmma::accumulator, 16, 16, 8, float> acc[6];
    #pragma unroll
    for (int j = 0; j < 6; j++) wmma::fill_fragment(acc[j], 0.0f);

    #pragma unroll
    for (int k = 0; k < D; k += 8) {
        wmma::fragment<wmma::matrix_a, 16, 16, 8, wmma::precision::tf32,
                       wmma::row_major> a_hi, a_lo;
        wmma::load_matrix_sync(a_hi, xs + warp * 16 * D + k, D);
        #pragma unroll
        for (int t = 0; t < a_hi.num_elements; t++) {
            float f  = a_hi.x[t];
            float hi = wmma::__float_to_tf32(f);
            a_hi.x[t] = hi;
            a_lo.x[t] = wmma::__float_to_tf32(f - hi);
        }
        #pragma unroll
        for (int j = 0; j < 6; j++) {
            wmma::fragment<wmma::matrix_b, 16, 16, 8, wmma::precision::tf32,
                           wmma::row_major> b_hi, b_lo;
            wmma::load_matrix_sync(b_hi, Wg + k * D + j * 16, D);
            #pragma unroll
            for (int t = 0; t < b_hi.num_elements; t++) {
                float f  = b_hi.x[t];
                float hi = wmma::__float_to_tf32(f);
                b_hi.x[t] = hi;
                b_lo.x[t] = wmma::__float_to_tf32(f - hi);
            }
            wmma::mma_sync(acc[j], a_hi, b_lo, acc[j]);
            wmma::mma_sync(acc[j], a_lo, b_hi, acc[j]);
            wmma::mma_sync(acc[j], a_hi, b_hi, acc[j]);
        }
    }

    __syncthreads();   // done reading xs as input
    #pragma unroll
    for (int j = 0; j < 6; j++)
        wmma::store_matrix_sync(xs + warp * 16 * D + j * 16, acc[j], D,
                                wmma::mem_row_major);
    __syncthreads();

    // epilogue: scale by inv_sqrt(deg_out), write h
    for (int i = tid; i < GROWS * D4; i += 192) {
        int r = i / D4, c = i % D4;
        int row = rbase + r;
        if (row < N_NODES) {
            float dg  = (float)g_deg_out_i[row];
            float inv = dg > 0.f ? rsqrtf(dg) : 0.f;
            float4 v = ((float4*)xs)[i];
            float4 o = make_float4(v.x * inv, v.y * inv, v.z * inv, v.w * inv);
            ((float4*)&g_h[(size_t)row * D])[c] = o;
        }
    }
}

// ---- kernel: aggregate per dst node (one warp/node, float4 lanes) ----
__global__ __launch_bounds__(256)
void k_agg(const float* __restrict__ b, float* __restrict__ out) {
    int warp = (blockIdx.x * blockDim.x + threadIdx.x) >> 5;
    int lane = threadIdx.x & 31;
    if (warp >= N_NODES) return;

    int beg = g_row_ptr[warp];
    int end = g_row_ptr[warp + 1];

    if (lane < D4) {
        float4 a = make_float4(0.f, 0.f, 0.f, 0.f);
        const float4* hbase = (const float4*)g_h;
        int j = beg;
        for (; j + 3 < end; j += 4) {
            int s0 = __ldg(&g_csr_src[j]);
            int s1 = __ldg(&g_csr_src[j + 1]);
            int s2 = __ldg(&g_csr_src[j + 2]);
            int s3 = __ldg(&g_csr_src[j + 3]);
            float4 v0 = __ldg(hbase + (size_t)s0 * D4 + lane);
            float4 v1 = __ldg(hbase + (size_t)s1 * D4 + lane);
            float4 v2 = __ldg(hbase + (size_t)s2 * D4 + lane);
            float4 v3 = __ldg(hbase + (size_t)s3 * D4 + lane);
            a.x += (v0.x + v1.x) + (v2.x + v3.x);
            a.y += (v0.y + v1.y) + (v2.y + v3.y);
            a.z += (v0.z + v1.z) + (v2.z + v3.z);
            a.w += (v0.w + v1.w) + (v2.w + v3.w);
        }
        for (; j < end; j++) {
            int s = __ldg(&g_csr_src[j]);
            float4 v = __ldg(hbase + (size_t)s * D4 + lane);
            a.x += v.x; a.y += v.y; a.z += v.z; a.w += v.w;
        }

        float dg  = (float)(end - beg);
        float inv = dg > 0.f ? rsqrtf(dg) : 0.f;
        float4 bb = ((const float4*)b)[lane];
        float4 o  = make_float4(a.x * inv + bb.x, a.y * inv + bb.y,
                                a.z * inv + bb.z, a.w * inv + bb.w);
        ((float4*)(out + (size_t)warp * D))[lane] = o;
    }

    // restore zero-invariant for the next graph replay
    if (lane == 30) {
        g_deg_in_i[warp]  = 0;
        g_deg_out_i[warp] = 0;
    }
}

extern "C" void kernel_launch(void* const* d_in, const int* in_sizes, int n_in,
                              void* d_out, int out_size) {
    const float* x   = (const float*)d_in[0];
    const float* W   = (const float*)d_in[1];
    const float* b   = (const float*)d_in[2];
    const int*   src = (const int*)d_in[3];
    const int*   dst = (const int*)d_in[4];
    float* out = (float*)d_out;
    const int E = in_sizes[3];

    cudaStream_t s2;
    cudaStreamCreateWithFlags(&s2, cudaStreamNonBlocking);
    cudaEvent_t ev_root, ev_gemm;
    cudaEventCreateWithFlags(&ev_root, cudaEventDisableTiming);
    cudaEventCreateWithFlags(&ev_gemm, cudaEventDisableTiming);

    // fork immediately: s2 = deg_out -> gemm;  main = deg_in -> scan -> fill
    cudaEventRecord(ev_root, 0);
    cudaStreamWaitEvent(s2, ev_root, 0);

    k_deg_out<<<(E + 255) / 256, 256, 0, s2>>>(src, E);
    k_gemm<<<(N_NODES + GROWS - 1) / GROWS, 192, 0, s2>>>(x, W);
    cudaEventRecord(ev_gemm, s2);

    k_deg_in<<<(E + 255) / 256, 256>>>(dst, E);
    k_scan1<<<NBLK, 256>>>();
    k_scan23<<<NBLK, 256>>>(E);
    k_fill<<<(E + 255) / 256, 256>>>(src, dst, E);

    cudaStreamWaitEvent(0, ev_gemm, 0);
    long long agg_threads = (long long)N_NODES * 32;
    k_agg<<<(int)((agg_threads + 255) / 256), 256>>>(b, out);
}